// round 17
// baseline (speedup 1.0000x reference)
#include <cuda_runtime.h>
#include <cuda_fp16.h>
#include <math.h>
#include <stdint.h>
#include <mma.h>

using namespace nvcuda;

// Problem constants
#define B_     64
#define NTOK   256
#define C_     1024
#define H_     16
#define DH_    64
#define DFF_   4096
#define MTOK   (B_*NTOK)          // 16384 tokens
#define EPS_   1e-5f

// ---------------------------------------------------------------------------
// Scratch
// ---------------------------------------------------------------------------
__device__ __half g_lnh [(size_t)MTOK * C_];         //  32 MB LN out (fp16)
__device__ __half g_qkvh[(size_t)MTOK * 3 * C_];     //  96 MB qkv (fp16)
__device__ __half g_attnh[(size_t)MTOK * C_];        //  32 MB merged attn (fp16)
__device__ float  g_x1  [(size_t)MTOK * C_];         //  64 MB post-attn residual
__device__ __half g_ffh [(size_t)MTOK * DFF_];       // 128 MB MLP hidden (fp16)
__device__ __half g_wh  [(size_t)12 * 1024 * 1024];  //  24 MB fp16 weights
__device__ float  g_bias[(size_t)H_ * NTOK * NTOK];  //   4 MB gathered rel bias

// ---------------------------------------------------------------------------
// helpers
// ---------------------------------------------------------------------------
__device__ __forceinline__ uint32_t smem_u32(const void* p) {
    uint32_t a;
    asm("{ .reg .u64 t; cvta.to.shared.u64 t, %1; cvt.u32.u64 %0, t; }"
        : "=r"(a) : "l"(p));
    return a;
}
#define CP_ASYNC16(dst, src) \
    asm volatile("cp.async.cg.shared.global [%0], [%1], 16;" :: "r"(dst), "l"(src))
#define CP_COMMIT() asm volatile("cp.async.commit_group;" ::: "memory")
#define CP_WAIT1()  asm volatile("cp.async.wait_group 1;" ::: "memory")

__device__ __forceinline__ float tanh_fast(float x) {
    float y;
    asm("tanh.approx.f32 %0, %1;" : "=f"(y) : "f"(x));
    return y;
}

__global__ __launch_bounds__(256) void f2h_kernel(
    const float* __restrict__ src, __half* __restrict__ dst, int n4)
{
    const int i = blockIdx.x * 256 + threadIdx.x;
    if (i < n4) {
        const float4 v = reinterpret_cast<const float4*>(src)[i];
        reinterpret_cast<__half2*>(dst)[i * 2 + 0] = __floats2half2_rn(v.x, v.y);
        reinterpret_cast<__half2*>(dst)[i * 2 + 1] = __floats2half2_rn(v.z, v.w);
    }
}

// gathered bias: bf[h][n*256+m] = rel_bias[rel_idx[n*256+m]*H + h]
__global__ __launch_bounds__(256) void bias_gather_kernel(
    const int* __restrict__ rel_idx, const float* __restrict__ rel_bias,
    float* __restrict__ bf)
{
    const int i = blockIdx.x * 256 + threadIdx.x;   // 0..65535
    const int h = blockIdx.y;
    bf[(size_t)h * (NTOK * NTOK) + i] = rel_bias[rel_idx[i] * H_ + h];
}

// ---------------------------------------------------------------------------
// LayerNorm: warp per token (8 tokens/block), fp32 in, fp16 out
// ---------------------------------------------------------------------------
__global__ __launch_bounds__(256) void ln_kernel(
    const float* __restrict__ x, const float* __restrict__ g,
    const float* __restrict__ b, __half* __restrict__ out)
{
    const int tok  = blockIdx.x * 8 + (threadIdx.x >> 5);
    const int lane = threadIdx.x & 31;
    const float4* xr = reinterpret_cast<const float4*>(x + (size_t)tok * C_);

    float4 v[8];
    float s = 0.0f, ss = 0.0f;
    #pragma unroll
    for (int j = 0; j < 8; j++) {
        v[j] = xr[lane + j * 32];
        s  += v[j].x + v[j].y + v[j].z + v[j].w;
        ss += v[j].x*v[j].x + v[j].y*v[j].y + v[j].z*v[j].z + v[j].w*v[j].w;
    }
    #pragma unroll
    for (int o = 16; o > 0; o >>= 1) {
        s  += __shfl_xor_sync(0xffffffffu, s,  o, 32);
        ss += __shfl_xor_sync(0xffffffffu, ss, o, 32);
    }
    const float mu  = s * (1.0f / C_);
    const float var = ss * (1.0f / C_) - mu * mu;
    const float inv = rsqrtf(var + EPS_);

    const float4* gr = reinterpret_cast<const float4*>(g);
    const float4* br = reinterpret_cast<const float4*>(b);
    __half2* orow = reinterpret_cast<__half2*>(out + (size_t)tok * C_);
    #pragma unroll
    for (int j = 0; j < 8; j++) {
        const float4 gv = gr[lane + j * 32];
        const float4 bv = br[lane + j * 32];
        const int idx = (lane + j * 32) * 2;
        orow[idx + 0] = __floats2half2_rn((v[j].x - mu) * inv * gv.x + bv.x,
                                          (v[j].y - mu) * inv * gv.y + bv.y);
        orow[idx + 1] = __floats2half2_rn((v[j].z - mu) * inv * gv.z + bv.z,
                                          (v[j].w - mu) * inv * gv.w + bv.w);
    }
}

// ---------------------------------------------------------------------------
// FP16 WMMA GEMM, 3-stage cp.async pipeline, 128x256 block tile.
// 8 warps (2x4), 64x64 per warp (4x4 fragments) -> HMMA/LDSM density 4.
// out[M,N] = A[M,K](fp16) @ W[K,N](fp16) + bias (+gelu->fp16 | +res->fp32)
// ---------------------------------------------------------------------------
enum { EPI_BIAS = 0, EPI_GELU = 1, EPI_RES = 2 };

__device__ __forceinline__ float gelu_tanh(float x) {
    const float k0 = 0.7978845608028654f;
    float x3 = x * x * x;
    return 0.5f * x * (1.0f + tanh_fast(k0 * (x + 0.044715f * x3)));
}

#define HLDA 40    // As row stride (halves): 80B, banks 20r%32 distinct
#define HLDB 264   // Bs row stride (halves): 528B, banks 4r%32 distinct
#define LDC2 72    // epilogue stage row stride (floats)
#define AS_BYTES (3 * 128 * HLDA * 2)              // 30720
#define BS_BYTES (3 * 32 * HLDB * 2)               // 50688
#define SMEM_GEMM (AS_BYTES + BS_BYTES)            // 81408 (Cst 36864 aliases)

template <int EPI, typename OutT>
__global__ __launch_bounds__(256, 1) void hgemm(
    const __half* __restrict__ A, const __half* __restrict__ W,
    const float* __restrict__ bias, const float* __restrict__ res,
    OutT* __restrict__ out, int M, int N, int K)
{
    extern __shared__ char dynsm[];
    typedef __half AsT[128][HLDA];
    typedef __half BsT[32][HLDB];
    AsT* As = reinterpret_cast<AsT*>(dynsm);                // [3][128][HLDA]
    BsT* Bs = reinterpret_cast<BsT*>(dynsm + AS_BYTES);     // [3][32][HLDB]
    float (*Cst)[16][LDC2] =
        reinterpret_cast<float(*)[16][LDC2]>(dynsm);        // epilogue alias

    const int tid  = threadIdx.x;
    const int wid  = tid >> 5;
    const int lane = tid & 31;
    const int warp_m = wid & 1;       // 2 slabs of 64 rows
    const int warp_n = wid >> 1;      // 4 slabs of 64 cols
    const int row0 = blockIdx.y * 128;
    const int col0 = blockIdx.x * 256;

    // A loader: row = tid>>1, halves [(tid&1)*16, +16)  (2 x 16B chunks)
    const int arow = tid >> 1;
    const int acol = (tid & 1) * 16;
    const __half* Ap = A + (size_t)(row0 + arow) * K + acol;
    // B loader: k-row = tid>>3, halves [(tid&7)*32, +32) (4 x 16B chunks)
    const int brow = tid >> 3;
    const int bcol = (tid & 7) * 32;
    const __half* Wp = W + (size_t)brow * N + col0 + bcol;

    uint32_t uA[3], uB[3];
    #pragma unroll
    for (int s = 0; s < 3; s++) {
        uA[s] = smem_u32(&As[s][arow][acol]);
        uB[s] = smem_u32(&Bs[s][brow][bcol]);
    }

    wmma::fragment<wmma::accumulator, 16, 16, 16, float> c[4][4];
    #pragma unroll
    for (int mi = 0; mi < 4; mi++)
        #pragma unroll
        for (int nj = 0; nj < 4; nj++)
            wmma::fill_fragment(c[mi][nj], 0.0f);

    const int n_iter = K >> 5;   // BK = 32

    // prologue: tiles 0,1 -> stages 0,1
    #pragma unroll
    for (int s = 0; s < 2; s++) {
        const size_t koff = (size_t)s * 32;
        CP_ASYNC16(uA[s],      Ap + koff);
        CP_ASYNC16(uA[s] + 16, Ap + koff + 8);
        CP_ASYNC16(uB[s],      Wp + koff * N);
        CP_ASYNC16(uB[s] + 16, Wp + koff * N + 8);
        CP_ASYNC16(uB[s] + 32, Wp + koff * N + 16);
        CP_ASYNC16(uB[s] + 48, Wp + koff * N + 24);
        CP_COMMIT();
    }

    int st = 0;
    for (int it = 0; it < n_iter; ++it) {
        CP_WAIT1();          // tile `it` resident (<=1 group pending)
        __syncthreads();

        if (it + 2 < n_iter) {
            const int ns = (st + 2 >= 3) ? st - 1 : st + 2;
            const size_t koff = (size_t)(it + 2) << 5;
            CP_ASYNC16(uA[ns],      Ap + koff);
            CP_ASYNC16(uA[ns] + 16, Ap + koff + 8);
            CP_ASYNC16(uB[ns],      Wp + koff * N);
            CP_ASYNC16(uB[ns] + 16, Wp + koff * N + 8);
            CP_ASYNC16(uB[ns] + 32, Wp + koff * N + 16);
            CP_ASYNC16(uB[ns] + 48, Wp + koff * N + 24);
        }
        CP_COMMIT();         // uniform group count per iter

        #pragma unroll
        for (int kk = 0; kk < 32; kk += 16) {
            wmma::fragment<wmma::matrix_b, 16, 16, 16, __half, wmma::row_major> bf[4];
            #pragma unroll
            for (int nj = 0; nj < 4; nj++)
                wmma::load_matrix_sync(bf[nj], &Bs[st][kk][warp_n * 64 + nj * 16], HLDB);
            #pragma unroll
            for (int mi = 0; mi < 4; mi++) {
                wmma::fragment<wmma::matrix_a, 16, 16, 16, __half, wmma::row_major> af;
                wmma::load_matrix_sync(af, &As[st][warp_m * 64 + mi * 16][kk], HLDA);
                #pragma unroll
                for (int nj = 0; nj < 4; nj++)
                    wmma::mma_sync(c[mi][nj], af, bf[nj], c[mi][nj]);
            }
        }
        st = (st + 1 == 3) ? 0 : st + 1;
    }
    __syncthreads();   // compute done everywhere before Cst aliases stages

    // Epilogue: per warp stage 16x64 slabs, two coalesced col-stores per lane
    const int cg0 = col0 + warp_n * 64 + lane;
    const float bv0 = bias[cg0];
    const float bv1 = bias[cg0 + 32];
    #pragma unroll
    for (int mi = 0; mi < 4; mi++) {
        #pragma unroll
        for (int nj = 0; nj < 4; nj++)
            wmma::store_matrix_sync(&Cst[wid][0][nj * 16], c[mi][nj], LDC2,
                                    wmma::mem_row_major);
        __syncwarp();
        const int rg0 = row0 + warp_m * 64 + mi * 16;
        #pragma unroll
        for (int rr = 0; rr < 16; rr++) {
            const int rg = rg0 + rr;
            float v0 = Cst[wid][rr][lane]      + bv0;
            float v1 = Cst[wid][rr][lane + 32] + bv1;
            if (EPI == EPI_GELU) { v0 = gelu_tanh(v0); v1 = gelu_tanh(v1); }
            if (EPI == EPI_RES) {
                v0 += res[(size_t)rg * N + cg0];
                v1 += res[(size_t)rg * N + cg0 + 32];
            }
            if (sizeof(OutT) == 2) {
                out[(size_t)rg * N + cg0]      = (OutT)__float2half(v0);
                out[(size_t)rg * N + cg0 + 32] = (OutT)__float2half(v1);
            } else {
                out[(size_t)rg * N + cg0]      = (OutT)v0;
                out[(size_t)rg * N + cg0 + 32] = (OutT)v1;
            }
        }
        __syncwarp();
    }
}

// ---------------------------------------------------------------------------
// Fused tensor-core attention (R10, known-good)
// ---------------------------------------------------------------------------
#define QLD 72
#define KLD 72
#define VLD 72
#define SLD 264
#define PLD 280
#define OFF_Q 0
#define OFF_K (OFF_Q + 64 * QLD * 2)
#define OFF_V (OFF_K + 256 * KLD * 2)
#define OFF_S (OFF_V + 256 * VLD * 2)
#define SMEM_ATTN (OFF_S + 64 * SLD * 4)

__global__ __launch_bounds__(256) void attn_kernel(
    const __half* __restrict__ qkv, const float* __restrict__ bias_full,
    __half* __restrict__ attn_out)
{
    extern __shared__ char dyn[];
    __half* Qs = reinterpret_cast<__half*>(dyn + OFF_Q);
    __half* Ks = reinterpret_cast<__half*>(dyn + OFF_K);
    __half* Vs = reinterpret_cast<__half*>(dyn + OFF_V);
    float*  Ss = reinterpret_cast<float*>(dyn + OFF_S);
    __half* Ps = reinterpret_cast<__half*>(dyn + OFF_K);   // alias K
    float*  St = reinterpret_cast<float*>(dyn + OFF_S);    // PV stage, alias S

    const int bh = blockIdx.x;
    const int b  = bh >> 4, h = bh & 15;
    const int n0 = blockIdx.y * 64;
    const int tid = threadIdx.x;
    const int wid = tid >> 5;

    #pragma unroll
    for (int i = tid; i < 64 * 8; i += 256) {
        const int r = i >> 3, c8 = (i & 7) * 8;
        *reinterpret_cast<float4*>(&Qs[r * QLD + c8]) =
            *reinterpret_cast<const float4*>(
                qkv + (size_t)(b * NTOK + n0 + r) * (3 * C_) + h * DH_ + c8);
    }
    #pragma unroll
    for (int i = tid; i < 256 * 8; i += 256) {
        const int r = i >> 3, c8 = (i & 7) * 8;
        *reinterpret_cast<float4*>(&Ks[r * KLD + c8]) =
            *reinterpret_cast<const float4*>(
                qkv + (size_t)(b * NTOK + r) * (3 * C_) + C_ + h * DH_ + c8);
        *reinterpret_cast<float4*>(&Vs[r * VLD + c8]) =
            *reinterpret_cast<const float4*>(
                qkv + (size_t)(b * NTOK + r) * (3 * C_) + 2 * C_ + h * DH_ + c8);
    }
    __syncthreads();

    {
        const int warp_m = wid & 1;
        const int warp_n = wid >> 1;
        wmma::fragment<wmma::accumulator, 16, 16, 16, float> acc[2][4];
        #pragma unroll
        for (int mi = 0; mi < 2; mi++)
            #pragma unroll
            for (int nj = 0; nj < 4; nj++)
                wmma::fill_fragment(acc[mi][nj], 0.0f);
        #pragma unroll
        for (int kk = 0; kk < 64; kk += 16) {
            wmma::fragment<wmma::matrix_a, 16, 16, 16, __half, wmma::row_major> af[2];
            wmma::fragment<wmma::matrix_b, 16, 16, 16, __half, wmma::col_major> bf[4];
            #pragma unroll
            for (int mi = 0; mi < 2; mi++)
                wmma::load_matrix_sync(af[mi], &Qs[(warp_m * 32 + mi * 16) * QLD + kk], QLD);
            #pragma unroll
            for (int nj = 0; nj < 4; nj++)
                wmma::load_matrix_sync(bf[nj], &Ks[(warp_n * 64 + nj * 16) * KLD + kk], KLD);
            #pragma unroll
            for (int mi = 0; mi < 2; mi++)
                #pragma unroll
                for (int nj = 0; nj < 4; nj++)
                    wmma::mma_sync(acc[mi][nj], af[mi], bf[nj], acc[mi][nj]);
        }
        #pragma unroll
        for (int mi = 0; mi < 2; mi++)
            #pragma unroll
            for (int nj = 0; nj < 4; nj++)
                wmma::store_matrix_sync(
                    &Ss[(warp_m * 32 + mi * 16) * SLD + warp_n * 64 + nj * 16],
                    acc[mi][nj], SLD, wmma::mem_row_major);
    }
    __syncthreads();

    {
        const int r  = tid >> 2;
        const int qq = tid & 3;
        const float* bias_row = bias_full + (size_t)h * (NTOK * NTOK)
                              + (size_t)(n0 + r) * NTOK + qq * 64;
        float* srow = &Ss[r * SLD + qq * 64];

        float vmax = -1e30f;
        #pragma unroll
        for (int j = 0; j < 16; j++) {
            float4 s = *reinterpret_cast<float4*>(srow + j * 4);
            const float4 bb = *reinterpret_cast<const float4*>(bias_row + j * 4);
            s.x = s.x * 0.125f + bb.x; s.y = s.y * 0.125f + bb.y;
            s.z = s.z * 0.125f + bb.z; s.w = s.w * 0.125f + bb.w;
            *reinterpret_cast<float4*>(srow + j * 4) = s;
            vmax = fmaxf(vmax, fmaxf(fmaxf(s.x, s.y), fmaxf(s.z, s.w)));
        }
        vmax = fmaxf(vmax, __shfl_xor_sync(0xffffffffu, vmax, 1, 32));
        vmax = fmaxf(vmax, __shfl_xor_sync(0xffffffffu, vmax, 2, 32));

        float ssum = 0.0f;
        #pragma unroll
        for (int j = 0; j < 16; j++) {
            float4 s = *reinterpret_cast<float4*>(srow + j * 4);
            s.x = __expf(s.x - vmax); s.y = __expf(s.y - vmax);
            s.z = __expf(s.z - vmax); s.w = __expf(s.w - vmax);
            *reinterpret_cast<float4*>(srow + j * 4) = s;
            ssum += s.x + s.y + s.z + s.w;
        }
        ssum += __shfl_xor_sync(0xffffffffu, ssum, 1, 32);
        ssum += __shfl_xor_sync(0xffffffffu, ssum, 2, 32);
        const float inv = 1.0f / ssum;

        __half* prow = &Ps[r * PLD + qq * 64];
        #pragma unroll
        for (int j = 0; j < 16; j++) {
            const float4 s = *reinterpret_cast<float4*>(srow + j * 4);
            *reinterpret_cast<__half2*>(prow + j * 4)     = __floats2half2_rn(s.x * inv, s.y * inv);
            *reinterpret_cast<__half2*>(prow + j * 4 + 2) = __floats2half2_rn(s.z * inv, s.w * inv);
        }
    }
    __syncthreads();

    {
        const int warp_m = wid >> 1;
        const int warp_n = wid & 1;
        wmma::fragment<wmma::accumulator, 16, 16, 16, float> acc[2];
        wmma::fill_fragment(acc[0], 0.0f);
        wmma::fill_fragment(acc[1], 0.0f);
        #pragma unroll
        for (int k0 = 0; k0 < 256; k0 += 16) {
            wmma::fragment<wmma::matrix_a, 16, 16, 16, __half, wmma::row_major> af;
            wmma::load_matrix_sync(af, &Ps[(warp_m * 16) * PLD + k0], PLD);
            #pragma unroll
            for (int nj = 0; nj < 2; nj++) {
                wmma::fragment<wmma::matrix_b, 16, 16, 16, __half, wmma::row_major> bf;
                wmma::load_matrix_sync(bf, &Vs[k0 * VLD + warp_n * 32 + nj * 16], VLD);
                wmma::mma_sync(acc[nj], af, bf, acc[nj]);
            }
        }
        __syncthreads();
        #pragma unroll
        for (int nj = 0; nj < 2; nj++)
            wmma::store_matrix_sync(
                &St[(warp_m * 16) * QLD + warp_n * 32 + nj * 16],
                acc[nj], QLD, wmma::mem_row_major);
    }
    __syncthreads();

    {
        const int r  = tid >> 2;
        const int c0 = (tid & 3) * 16;
        __half tmp[16];
        #pragma unroll
        for (int j = 0; j < 16; j++)
            tmp[j] = __float2half(St[r * QLD + c0 + j]);
        __half* dst = attn_out + (size_t)(b * NTOK + n0 + r) * C_ + h * DH_ + c0;
        *reinterpret_cast<uint4*>(dst)     = *reinterpret_cast<uint4*>(&tmp[0]);
        *reinterpret_cast<uint4*>(dst + 8) = *reinterpret_cast<uint4*>(&tmp[8]);
    }
}

// ---------------------------------------------------------------------------
// Launch
// ---------------------------------------------------------------------------
extern "C" void kernel_launch(void* const* d_in, const int* in_sizes, int n_in,
                              void* d_out, int out_size)
{
    const float* x        = (const float*)d_in[0];
    const int*   rel_idx  = (const int*)  d_in[1];
    const float* qkv_w    = (const float*)d_in[2];
    const float* qkv_b    = (const float*)d_in[3];
    const float* proj_w   = (const float*)d_in[4];
    const float* proj_b   = (const float*)d_in[5];
    const float* rel_bias = (const float*)d_in[6];
    const float* ln1_g    = (const float*)d_in[7];
    const float* ln1_b    = (const float*)d_in[8];
    const float* ln2_g    = (const float*)d_in[9];
    const float* ln2_b    = (const float*)d_in[10];
    const float* fc1_w    = (const float*)d_in[11];
    const float* fc1_b    = (const float*)d_in[12];
    const float* fc2_w    = (const float*)d_in[13];
    const float* fc2_b    = (const float*)d_in[14];
    float* out = (float*)d_out;

    __half *lnh, *qkvh, *attnh, *ffh, *wh;
    float *x1, *biasf;
    cudaGetSymbolAddress((void**)&lnh,   g_lnh);
    cudaGetSymbolAddress((void**)&qkvh,  g_qkvh);
    cudaGetSymbolAddress((void**)&attnh, g_attnh);
    cudaGetSymbolAddress((void**)&x1,    g_x1);
    cudaGetSymbolAddress((void**)&ffh,   g_ffh);
    cudaGetSymbolAddress((void**)&wh,    g_wh);
    cudaGetSymbolAddress((void**)&biasf, g_bias);

    __half* qkv_wh  = wh;
    __half* proj_wh = wh + (size_t)3 * 1024 * 1024;
    __half* fc1_wh  = wh + (size_t)4 * 1024 * 1024;
    __half* fc2_wh  = wh + (size_t)8 * 1024 * 1024;

    cudaFuncSetAttribute(attn_kernel,
        cudaFuncAttributeMaxDynamicSharedMemorySize, SMEM_ATTN);
    cudaFuncSetAttribute(hgemm<EPI_BIAS, __half>,
        cudaFuncAttributeMaxDynamicSharedMemorySize, SMEM_GEMM);
    cudaFuncSetAttribute(hgemm<EPI_RES, float>,
        cudaFuncAttributeMaxDynamicSharedMemorySize, SMEM_GEMM);
    cudaFuncSetAttribute(hgemm<EPI_GELU, __half>,
        cudaFuncAttributeMaxDynamicSharedMemorySize, SMEM_GEMM);

    // 0) weight conversion + bias gather
    f2h_kernel<<<(3 * 1024 * 1024 / 4 + 255) / 256, 256>>>(qkv_w, qkv_wh, 3 * 1024 * 1024 / 4);
    f2h_kernel<<<(1024 * 1024 / 4 + 255) / 256, 256>>>(proj_w, proj_wh, 1024 * 1024 / 4);
    f2h_kernel<<<(4 * 1024 * 1024 / 4 + 255) / 256, 256>>>(fc1_w, fc1_wh, 4 * 1024 * 1024 / 4);
    f2h_kernel<<<(4 * 1024 * 1024 / 4 + 255) / 256, 256>>>(fc2_w, fc2_wh, 4 * 1024 * 1024 / 4);
    bias_gather_kernel<<<dim3(NTOK * NTOK / 256, H_), 256>>>(rel_idx, rel_bias, biasf);

    // 1) LN1 -> fp16
    ln_kernel<<<MTOK / 8, 256>>>(x, ln1_g, ln1_b, lnh);
    // 2) QKV GEMM -> fp16 qkv
    hgemm<EPI_BIAS, __half><<<dim3(3 * C_ / 256, MTOK / 128), 256, SMEM_GEMM>>>(
        lnh, qkv_wh, qkv_b, nullptr, qkvh, MTOK, 3 * C_, C_);
    // 3) fused attention -> fp16 merged heads
    attn_kernel<<<dim3(B_ * H_, NTOK / 64), 256, SMEM_ATTN>>>(qkvh, biasf, attnh);
    // 4) proj + residual(x) -> x1 (fp32)
    hgemm<EPI_RES, float><<<dim3(C_ / 256, MTOK / 128), 256, SMEM_GEMM>>>(
        attnh, proj_wh, proj_b, x, x1, MTOK, C_, C_);
    // 5) LN2 -> fp16
    ln_kernel<<<MTOK / 8, 256>>>(x1, ln2_g, ln2_b, lnh);
    // 6) FC1 + GELU -> fp16
    hgemm<EPI_GELU, __half><<<dim3(DFF_ / 256, MTOK / 128), 256, SMEM_GEMM>>>(
        lnh, fc1_wh, fc1_b, nullptr, ffh, MTOK, DFF_, C_);
    // 7) FC2 + residual(x1) -> out (fp32)
    hgemm<EPI_RES, float><<<dim3(C_ / 256, MTOK / 128), 256, SMEM_GEMM>>>(
        ffh, fc2_wh, fc2_b, x1, out, MTOK, C_, DFF_);
}